// round 8
// baseline (speedup 1.0000x reference)
#include <cuda_runtime.h>
#include <cuda_fp16.h>
#include <math.h>
#include <stdint.h>

// ---------------- problem constants ----------------
#define BT      8
#define SEQ     576
#define MTOT    (BT * SEQ)        // 4608
#define NLF     25
#define DIM     2048              // D
#define CTD     1024              // CT
#define HEADS   8
#define HDIM    128
#define ATT_SCALE 0.03125f
#define LN_EPSF   1e-5f
#define COS_EPSF  1e-8f

// ---------------- device scratch ----------------
__device__ __half g_xn[(size_t)8 * MTOT * DIM];   // slots 0..6 LN'd layers, slot 7 raw layer 24
__device__ __half g_wh[(size_t)8 * DIM * CTD];    // slots 0..6 w_norm, slot 7 w_in (fp16)
__device__ __half g_woh[(size_t)CTD * CTD];       // w_out fp16
__device__ __half g_vh[(size_t)MTOT * 7 * CTD];   // vout slots 0..6, fp16, [m][slot][c]
__device__ float  g_vin[(size_t)MTOT * CTD];      // vin fp32
__device__ __half g_fuse[(size_t)MTOT * CTD];
__device__ float  g_vf[(size_t)MTOT * CTD];
__device__ float  g_cos[MTOT];

// ---------------- helpers ----------------
__device__ __forceinline__ float warp_sum(float v) {
#pragma unroll
    for (int o = 16; o > 0; o >>= 1) v += __shfl_xor_sync(0xffffffffu, v, o);
    return v;
}
__device__ __forceinline__ void cp16(void* dst, const void* src) {
    uint32_t d = (uint32_t)__cvta_generic_to_shared(dst);
    asm volatile("cp.async.cg.shared.global [%0], [%1], 16;\n" :: "r"(d), "l"(src));
}
__device__ __forceinline__ uint2 f4_to_h4(float4 v) {
    __half2 lo = __floats2half2_rn(v.x, v.y);
    __half2 hi = __floats2half2_rn(v.z, v.w);
    uint2 r;
    r.x = *reinterpret_cast<uint32_t*>(&lo);
    r.y = *reinterpret_cast<uint32_t*>(&hi);
    return r;
}

// ---------------- 0) convert weights to fp16 ----------------
#define WN4 ((size_t)7 * DIM * CTD / 4)
#define WI4 ((size_t)DIM * CTD / 4)
#define WO4 ((size_t)CTD * CTD / 4)
__global__ void __launch_bounds__(256) convert_weights(
    const float* __restrict__ wn, const float* __restrict__ wi,
    const float* __restrict__ wo)
{
    size_t i = (size_t)blockIdx.x * 256 + threadIdx.x;
    if (i < WN4) {
        reinterpret_cast<uint2*>(g_wh)[i] =
            f4_to_h4(reinterpret_cast<const float4*>(wn)[i]);
    } else if (i < WN4 + WI4) {
        size_t j = i - WN4;
        reinterpret_cast<uint2*>(g_wh + (size_t)7 * DIM * CTD)[j] =
            f4_to_h4(reinterpret_cast<const float4*>(wi)[j]);
    } else if (i < WN4 + WI4 + WO4) {
        size_t j = i - WN4 - WI4;
        reinterpret_cast<uint2*>(g_woh)[j] =
            f4_to_h4(reinterpret_cast<const float4*>(wo)[j]);
    }
}

// ---------------- 1) gather + layernorm -> fp16 ----------------
__global__ void __launch_bounds__(256) ln_kernel(
    const float* __restrict__ features,
    const float* __restrict__ ln_scale,
    const float* __restrict__ ln_bias)
{
    int l = blockIdx.x & 7;
    int m = blockIdx.x >> 3;
    int layer = (l < 7) ? (24 - 4 * l) : 24;
    const float4* x = reinterpret_cast<const float4*>(
        features + ((size_t)m * NLF + layer) * DIM);
    int t = threadIdx.x;

    float4 a = x[t];
    float4 b = x[t + 256];
    uint2* o = reinterpret_cast<uint2*>(g_xn + ((size_t)l * MTOT + m) * DIM);

    if (l == 7) {
        o[t] = f4_to_h4(a);
        o[t + 256] = f4_to_h4(b);
        return;
    }

    float s  = a.x + a.y + a.z + a.w + b.x + b.y + b.z + b.w;
    float ss = a.x*a.x + a.y*a.y + a.z*a.z + a.w*a.w
             + b.x*b.x + b.y*b.y + b.z*b.z + b.w*b.w;

    __shared__ float shs[8], shss[8];
    float ws  = warp_sum(s);
    float wss = warp_sum(ss);
    int w = t >> 5, lane = t & 31;
    if (lane == 0) { shs[w] = ws; shss[w] = wss; }
    __syncthreads();
    float tot = 0.f, tot2 = 0.f;
#pragma unroll
    for (int i = 0; i < 8; i++) { tot += shs[i]; tot2 += shss[i]; }

    float mu  = tot * (1.0f / DIM);
    float var = tot2 * (1.0f / DIM) - mu * mu;
    float rs  = rsqrtf(var + LN_EPSF);

    const float4* sc = reinterpret_cast<const float4*>(ln_scale + (size_t)l * DIM);
    const float4* bi = reinterpret_cast<const float4*>(ln_bias  + (size_t)l * DIM);
    float4 s0 = sc[t],       b0 = bi[t];
    float4 s1 = sc[t + 256], b1 = bi[t + 256];
    float4 o0, o1;
    o0.x = (a.x - mu) * rs * s0.x + b0.x;
    o0.y = (a.y - mu) * rs * s0.y + b0.y;
    o0.z = (a.z - mu) * rs * s0.z + b0.z;
    o0.w = (a.w - mu) * rs * s0.w + b0.w;
    o1.x = (b.x - mu) * rs * s1.x + b1.x;
    o1.y = (b.y - mu) * rs * s1.y + b1.y;
    o1.z = (b.z - mu) * rs * s1.z + b1.z;
    o1.w = (b.w - mu) * rs * s1.w + b1.w;
    o[t] = f4_to_h4(o0);
    o[t + 256] = f4_to_h4(o1);
}

// ---------------- 2) HFMA2 GEMM v3: 128x128x32 tile, 128 thr, 8Mx16N/thread -
// 2 CTAs/SM. A dup (v,v) half2 pairs in smem; B fp16 [K,N] natural via cp.async.
// half2 accumulators flushed to fp32 regs every 2 K-tiles (K=64).
// MODE 0: g_xn[z] @ g_wh[z] -> z<7: g_vh slot z (fp16); z==7: g_vin + b_in (fp32)
// MODE 1: g_fuse @ g_woh + vin + b_out -> g_vf
#define KT 32
template<int NKT, int MODE>
__global__ void __launch_bounds__(128, 2) gemm_h3(
    const float* __restrict__ bias)
{
    __shared__ __align__(16) uint32_t As2[2][KT][128];  // dup half2 pairs, 32 KB
    __shared__ __align__(16) __half   Bs[2][KT][128];   // 16 KB

    int tid = threadIdx.x;
    int m0 = blockIdx.y * 128, n0 = blockIdx.x * 128;
    int z = (MODE == 0) ? blockIdx.z : 0;

    const __half* A;
    const __half* B;
    if (MODE == 0) {
        A = g_xn + (size_t)z * MTOT * DIM;
        B = g_wh + (size_t)z * DIM * CTD;
    } else {
        A = g_fuse;
        B = g_woh;
    }
    const int lda = (MODE == 0) ? DIM : CTD;

    // A loader: one M-row per thread, 32 halves (4 uint4) per tile
    const __half* ag = A + (size_t)(m0 + tid) * lda;
    // B loader: 4 units of 16B per thread; unit u -> (krow = u>>4, col = (u&15)*8)
    int bu = tid * 4;
    const __half* bg = B + (size_t)(bu >> 4) * CTD + n0 + (bu & 15) * 8;
    // units bu..bu+3 share the same krow (bu multiple of 4, 16 units per row)

    // compute mapping: ty 0..15 (8 m-rows), tx 0..7 (16 n-cols)
    int ty = tid >> 3, tx = tid & 7;

    float2  accf[8][8];
    __half2 acch[8][8];
#pragma unroll
    for (int i = 0; i < 8; i++)
#pragma unroll
        for (int j = 0; j < 8; j++) {
            accf[i][j] = make_float2(0.f, 0.f);
            acch[i][j] = __half2half2(__ushort_as_half(0));
        }

    uint4 pa[4];

    auto store_a = [&](int buf) {
#pragma unroll
        for (int q = 0; q < 4; q++) {
            const __half2* hp = reinterpret_cast<const __half2*>(&pa[q]);
#pragma unroll
            for (int jj = 0; jj < 4; jj++) {
                __half2 dlo = __half2half2(__low2half(hp[jj]));
                __half2 dhi = __half2half2(__high2half(hp[jj]));
                As2[buf][q * 8 + 2 * jj][tid]     = *reinterpret_cast<uint32_t*>(&dlo);
                As2[buf][q * 8 + 2 * jj + 1][tid] = *reinterpret_cast<uint32_t*>(&dhi);
            }
        }
    };
    auto load_a = [&](int kt) {
#pragma unroll
        for (int q = 0; q < 4; q++)
            pa[q] = *reinterpret_cast<const uint4*>(ag + kt * KT + q * 8);
    };
    auto load_b = [&](int buf, int kt) {
        const __half* bsrc = bg + (size_t)kt * KT * CTD;
#pragma unroll
        for (int q = 0; q < 4; q++)
            cp16(&Bs[buf][bu >> 4][(bu & 15) * 8 + q * 8], bsrc + q * 8);
        asm volatile("cp.async.commit_group;\n" ::: "memory");
    };

    // ---- prologue: tile 0 into buf 0 ----
    load_a(0);
    load_b(0, 0);
    store_a(0);

    for (int kt = 0; kt < NKT; kt++) {
        int buf = kt & 1;
        asm volatile("cp.async.wait_group 0;\n" ::: "memory");
        __syncthreads();

        if (kt + 1 < NKT) {
            load_a(kt + 1);
            load_b(buf ^ 1, kt + 1);
        }

#pragma unroll 8
        for (int k = 0; k < KT; k++) {
            __half2 a2[8], b2[8];
            *reinterpret_cast<uint4*>(&a2[0]) =
                *reinterpret_cast<const uint4*>(&As2[buf][k][ty * 8]);
            *reinterpret_cast<uint4*>(&a2[4]) =
                *reinterpret_cast<const uint4*>(&As2[buf][k][ty * 8 + 4]);
            *reinterpret_cast<uint4*>(&b2[0]) =
                *reinterpret_cast<const uint4*>(&Bs[buf][k][tx * 16]);
            *reinterpret_cast<uint4*>(&b2[4]) =
                *reinterpret_cast<const uint4*>(&Bs[buf][k][tx * 16 + 8]);
#pragma unroll
            for (int i = 0; i < 8; i++)
#pragma unroll
                for (int j = 0; j < 8; j++)
                    acch[i][j] = __hfma2(a2[i], b2[j], acch[i][j]);
        }

        if (kt + 1 < NKT) store_a(buf ^ 1);

        if ((kt & 1) == 1 || kt == NKT - 1) {
#pragma unroll
            for (int i = 0; i < 8; i++)
#pragma unroll
                for (int j = 0; j < 8; j++) {
                    float2 t = __half22float2(acch[i][j]);
                    accf[i][j].x += t.x;
                    accf[i][j].y += t.y;
                    acch[i][j] = __half2half2(__ushort_as_half(0));
                }
        }
    }

    // ---- epilogue ----
#pragma unroll
    for (int i = 0; i < 8; i++) {
        int m = m0 + ty * 8 + i;
        int nb = n0 + tx * 16;
#pragma unroll
        for (int jj = 0; jj < 4; jj++) {
            int nn = nb + jj * 4;
            float4 v;
            v.x = accf[i][2 * jj].x;     v.y = accf[i][2 * jj].y;
            v.z = accf[i][2 * jj + 1].x; v.w = accf[i][2 * jj + 1].y;
            if (MODE == 0) {
                if (z < 7) {
                    uint2 hv = f4_to_h4(v);
                    *reinterpret_cast<uint2*>(
                        g_vh + (size_t)m * (7 * CTD) + (size_t)z * CTD + nn) = hv;
                } else {
                    float4 bb = *reinterpret_cast<const float4*>(bias + nn);
                    v.x += bb.x; v.y += bb.y; v.z += bb.z; v.w += bb.w;
                    *reinterpret_cast<float4*>(g_vin + (size_t)m * CTD + nn) = v;
                }
            } else {
                float4 bb = *reinterpret_cast<const float4*>(bias + nn);
                float4 vin = *reinterpret_cast<const float4*>(
                    g_vin + (size_t)m * CTD + nn);
                v.x += bb.x + vin.x; v.y += bb.y + vin.y;
                v.z += bb.z + vin.z; v.w += bb.w + vin.w;
                *reinterpret_cast<float4*>(g_vf + (size_t)m * CTD + nn) = v;
            }
        }
    }
}

// ---------------- 3) attention fuse (fp16 in, fp16 out) ----------------
__global__ void __launch_bounds__(128) attn_kernel()
{
    int m = blockIdx.x, t = threadIdx.x;
    const __half* vrow = g_vh + (size_t)m * 7 * CTD;
    __shared__ float shp[6][4];
    __shared__ float slog[6];
    int w = t >> 5, lane = t & 31;

    for (int h = 0; h < HEADS; h++) {
        float q = __half2float(vrow[h * HDIM + t]) * ATT_SCALE;
        float kv[6];
#pragma unroll
        for (int l = 0; l < 6; l++)
            kv[l] = __half2float(vrow[(size_t)(l + 1) * CTD + h * HDIM + t]);
#pragma unroll
        for (int l = 0; l < 6; l++) {
            float p = warp_sum(q * kv[l]);
            if (lane == 0) shp[l][w] = p;
        }
        __syncthreads();
        if (t < 6) slog[t] = shp[t][0] + shp[t][1] + shp[t][2] + shp[t][3];
        __syncthreads();
        float mx = -1e30f;
#pragma unroll
        for (int l = 0; l < 6; l++) mx = fmaxf(mx, slog[l]);
        float e[6], sum = 0.f;
#pragma unroll
        for (int l = 0; l < 6; l++) { e[l] = expf(slog[l] - mx); sum += e[l]; }
        float inv = 1.0f / sum;
        float f = 0.f;
#pragma unroll
        for (int l = 0; l < 6; l++) f += (e[l] * inv) * kv[l];
        g_fuse[(size_t)m * CTD + h * HDIM + t] = __float2half_rn(f);
        __syncthreads();
    }
}

// ---------------- 5) per-row cosine ----------------
__global__ void __launch_bounds__(256) cos_kernel(const float* __restrict__ teacher)
{
    int m = blockIdx.x, t = threadIdx.x;
    const float4* a = reinterpret_cast<const float4*>(g_vf + (size_t)m * CTD);
    const float4* b = reinterpret_cast<const float4*>(teacher + (size_t)m * CTD);
    float4 x = a[t], y = b[t];
    float dot = x.x*y.x + x.y*y.y + x.z*y.z + x.w*y.w;
    float n1  = x.x*x.x + x.y*x.y + x.z*x.z + x.w*x.w;
    float n2  = y.x*y.x + y.y*y.y + y.z*y.z + y.w*y.w;

    __shared__ float sd[8], s1[8], s2[8];
    float wd = warp_sum(dot), w1 = warp_sum(n1), w2 = warp_sum(n2);
    int w = t >> 5, lane = t & 31;
    if (lane == 0) { sd[w] = wd; s1[w] = w1; s2[w] = w2; }
    __syncthreads();
    if (t == 0) {
        float td = 0.f, t1 = 0.f, t2 = 0.f;
#pragma unroll
        for (int i = 0; i < 8; i++) { td += sd[i]; t1 += s1[i]; t2 += s2[i]; }
        float na = fmaxf(sqrtf(t1), COS_EPSF);
        float nb = fmaxf(sqrtf(t2), COS_EPSF);
        g_cos[m] = td / (na * nb);
    }
}

// ---------------- 6) final deterministic reduction ----------------
__global__ void __launch_bounds__(512) final_kernel(float* __restrict__ out)
{
    __shared__ float sh[512];
    int t = threadIdx.x;
    float s = 0.f;
    for (int i = t; i < MTOT; i += 512) s += g_cos[i];
    sh[t] = s;
    __syncthreads();
    for (int o = 256; o > 0; o >>= 1) {
        if (t < o) sh[t] += sh[t + o];
        __syncthreads();
    }
    if (t == 0) out[0] = 1.0f - sh[0] / (float)MTOT;
}

// ---------------- launch ----------------
extern "C" void kernel_launch(void* const* d_in, const int* in_sizes, int n_in,
                              void* d_out, int out_size)
{
    const float* features = (const float*)d_in[0];
    const float* teacher  = (const float*)d_in[1];
    const float* ln_scale = (const float*)d_in[2];
    const float* ln_bias  = (const float*)d_in[3];
    const float* w_norm   = (const float*)d_in[4];
    const float* w_in     = (const float*)d_in[5];
    const float* b_in     = (const float*)d_in[6];
    const float* w_out    = (const float*)d_in[7];
    const float* b_out    = (const float*)d_in[8];
    float* out = (float*)d_out;

    size_t total4 = WN4 + WI4 + WO4;
    convert_weights<<<(unsigned)((total4 + 255) / 256), 256>>>(w_norm, w_in, w_out);
    ln_kernel<<<MTOT * 8, 256>>>(features, ln_scale, ln_bias);
    gemm_h3<DIM / KT, 0><<<dim3(CTD / 128, MTOT / 128, 8), 128>>>(b_in);
    attn_kernel<<<MTOT, 128>>>();
    gemm_h3<CTD / KT, 1><<<dim3(CTD / 128, MTOT / 128, 1), 128>>>(b_out);
    cos_kernel<<<MTOT, 256>>>(teacher);
    final_kernel<<<1, 512>>>(out);
}

// round 9
// speedup vs baseline: 1.0993x; 1.0993x over previous
#include <cuda_runtime.h>
#include <cuda_fp16.h>
#include <math.h>
#include <stdint.h>

// ---------------- problem constants ----------------
#define BT      8
#define SEQ     576
#define MTOT    (BT * SEQ)        // 4608
#define NLF     25
#define DIM     2048              // D
#define CTD     1024              // CT
#define HEADS   8
#define HDIM    128
#define ATT_SCALE 0.03125f
#define LN_EPSF   1e-5f
#define COS_EPSF  1e-8f

// ---------------- device scratch ----------------
__device__ __half g_xn[(size_t)8 * MTOT * DIM];   // slots 0..6 LN'd layers, slot 7 raw layer 24
__device__ __half g_wh[(size_t)8 * DIM * CTD];    // slots 0..6 w_norm, slot 7 w_in (fp16)
__device__ __half g_woh[(size_t)CTD * CTD];       // w_out fp16
__device__ __half g_vh[(size_t)MTOT * 7 * CTD];   // vout slots 0..6, fp16
__device__ float  g_vin[(size_t)MTOT * CTD];      // vin fp32
__device__ __half g_fuse[(size_t)MTOT * CTD];
__device__ float  g_vf[(size_t)MTOT * CTD];
__device__ float  g_cos[MTOT];

// ---------------- helpers ----------------
__device__ __forceinline__ float warp_sum(float v) {
#pragma unroll
    for (int o = 16; o > 0; o >>= 1) v += __shfl_xor_sync(0xffffffffu, v, o);
    return v;
}
__device__ __forceinline__ void cp16(void* dst, const void* src) {
    uint32_t d = (uint32_t)__cvta_generic_to_shared(dst);
    asm volatile("cp.async.cg.shared.global [%0], [%1], 16;\n" :: "r"(d), "l"(src));
}
__device__ __forceinline__ uint2 f4_to_h4(float4 v) {
    __half2 lo = __floats2half2_rn(v.x, v.y);
    __half2 hi = __floats2half2_rn(v.z, v.w);
    uint2 r;
    r.x = *reinterpret_cast<uint32_t*>(&lo);
    r.y = *reinterpret_cast<uint32_t*>(&hi);
    return r;
}

// ---------------- 0) convert weights to fp16 ----------------
#define WN4 ((size_t)7 * DIM * CTD / 4)
#define WI4 ((size_t)DIM * CTD / 4)
#define WO4 ((size_t)CTD * CTD / 4)
__global__ void __launch_bounds__(256) convert_weights(
    const float* __restrict__ wn, const float* __restrict__ wi,
    const float* __restrict__ wo)
{
    size_t i = (size_t)blockIdx.x * 256 + threadIdx.x;
    if (i < WN4) {
        reinterpret_cast<uint2*>(g_wh)[i] =
            f4_to_h4(reinterpret_cast<const float4*>(wn)[i]);
    } else if (i < WN4 + WI4) {
        size_t j = i - WN4;
        reinterpret_cast<uint2*>(g_wh + (size_t)7 * DIM * CTD)[j] =
            f4_to_h4(reinterpret_cast<const float4*>(wi)[j]);
    } else if (i < WN4 + WI4 + WO4) {
        size_t j = i - WN4 - WI4;
        reinterpret_cast<uint2*>(g_woh)[j] =
            f4_to_h4(reinterpret_cast<const float4*>(wo)[j]);
    }
}

// ---------------- 1) gather + layernorm -> fp16 ----------------
__global__ void __launch_bounds__(256) ln_kernel(
    const float* __restrict__ features,
    const float* __restrict__ ln_scale,
    const float* __restrict__ ln_bias)
{
    int l = blockIdx.x & 7;
    int m = blockIdx.x >> 3;
    int layer = (l < 7) ? (24 - 4 * l) : 24;
    const float4* x = reinterpret_cast<const float4*>(
        features + ((size_t)m * NLF + layer) * DIM);
    int t = threadIdx.x;

    float4 a = x[t];
    float4 b = x[t + 256];
    uint2* o = reinterpret_cast<uint2*>(g_xn + ((size_t)l * MTOT + m) * DIM);

    if (l == 7) {
        o[t] = f4_to_h4(a);
        o[t + 256] = f4_to_h4(b);
        return;
    }

    float s  = a.x + a.y + a.z + a.w + b.x + b.y + b.z + b.w;
    float ss = a.x*a.x + a.y*a.y + a.z*a.z + a.w*a.w
             + b.x*b.x + b.y*b.y + b.z*b.z + b.w*b.w;

    __shared__ float shs[8], shss[8];
    float ws  = warp_sum(s);
    float wss = warp_sum(ss);
    int w = t >> 5, lane = t & 31;
    if (lane == 0) { shs[w] = ws; shss[w] = wss; }
    __syncthreads();
    float tot = 0.f, tot2 = 0.f;
#pragma unroll
    for (int i = 0; i < 8; i++) { tot += shs[i]; tot2 += shss[i]; }

    float mu  = tot * (1.0f / DIM);
    float var = tot2 * (1.0f / DIM) - mu * mu;
    float rs  = rsqrtf(var + LN_EPSF);

    const float4* sc = reinterpret_cast<const float4*>(ln_scale + (size_t)l * DIM);
    const float4* bi = reinterpret_cast<const float4*>(ln_bias  + (size_t)l * DIM);
    float4 s0 = sc[t],       b0 = bi[t];
    float4 s1 = sc[t + 256], b1 = bi[t + 256];
    float4 o0, o1;
    o0.x = (a.x - mu) * rs * s0.x + b0.x;
    o0.y = (a.y - mu) * rs * s0.y + b0.y;
    o0.z = (a.z - mu) * rs * s0.z + b0.z;
    o0.w = (a.w - mu) * rs * s0.w + b0.w;
    o1.x = (b.x - mu) * rs * s1.x + b1.x;
    o1.y = (b.y - mu) * rs * s1.y + b1.y;
    o1.z = (b.z - mu) * rs * s1.z + b1.z;
    o1.w = (b.w - mu) * rs * s1.w + b1.w;
    o[t] = f4_to_h4(o0);
    o[t + 256] = f4_to_h4(o1);
}

// ---------------- 2) HFMA2 GEMM (R7 structure): 128x128x16, 128 thr --------
// 2 CTAs/SM. A dup (v,v) half2 pairs in smem; B fp16 [K,N] natural via cp.async.
// half2 accumulators flushed to fp32 regs every 8 K-tiles (K=128 window).
// MODE 0: g_xn[z] @ g_wh[z] -> z<7: g_vh slot z (fp16); z==7: g_vin + b_in
// MODE 1: g_fuse @ g_woh + vin + b_out -> g_vf
template<int NKT, int MODE>
__global__ void __launch_bounds__(128, 2) gemm_h2(
    const float* __restrict__ bias)
{
    __shared__ __align__(16) uint32_t As2[2][16][128];  // dup half2 pairs, 16 KB
    __shared__ __align__(16) __half   Bs[2][16][128];   // 8 KB

    int tid = threadIdx.x;
    int m0 = blockIdx.y * 128, n0 = blockIdx.x * 128;
    int z = (MODE == 0) ? blockIdx.z : 0;

    const __half* A;
    const __half* B;
    if (MODE == 0) {
        A = g_xn + (size_t)z * MTOT * DIM;
        B = g_wh + (size_t)z * DIM * CTD;
    } else {
        A = g_fuse;
        B = g_woh;
    }
    const int lda = (MODE == 0) ? DIM : CTD;

    // A loader: one M-row per thread, 16 halves (2 uint4) per tile
    const __half* ag = A + (size_t)(m0 + tid) * lda;
    // B loader: 2 units of 16B per thread
    int bu = tid * 2;
    int br0 = bu >> 4,       bc0 = (bu & 15) * 8;
    int br1 = (bu + 1) >> 4, bc1 = ((bu + 1) & 15) * 8;
    const __half* bg0 = B + (size_t)br0 * CTD + n0 + bc0;
    const __half* bg1 = B + (size_t)br1 * CTD + n0 + bc1;

    // compute mapping: ty 0..15 (8 m-rows), tx 0..7 (16 n-cols)
    int ty = tid >> 3, tx = tid & 7;

    float2  accf[8][8];
    __half2 acch[8][8];
#pragma unroll
    for (int i = 0; i < 8; i++)
#pragma unroll
        for (int j = 0; j < 8; j++) {
            accf[i][j] = make_float2(0.f, 0.f);
            acch[i][j] = __half2half2(__ushort_as_half(0));
        }

    uint4 pa0, pa1;

    auto store_a = [&](int buf, uint4 r0, uint4 r1) {
        const __half2* h0 = reinterpret_cast<const __half2*>(&r0);
        const __half2* h1 = reinterpret_cast<const __half2*>(&r1);
#pragma unroll
        for (int jj = 0; jj < 4; jj++) {
            __half2 dlo = __half2half2(__low2half(h0[jj]));
            __half2 dhi = __half2half2(__high2half(h0[jj]));
            As2[buf][2 * jj][tid]     = *reinterpret_cast<uint32_t*>(&dlo);
            As2[buf][2 * jj + 1][tid] = *reinterpret_cast<uint32_t*>(&dhi);
        }
#pragma unroll
        for (int jj = 0; jj < 4; jj++) {
            __half2 dlo = __half2half2(__low2half(h1[jj]));
            __half2 dhi = __half2half2(__high2half(h1[jj]));
            As2[buf][8 + 2 * jj][tid]     = *reinterpret_cast<uint32_t*>(&dlo);
            As2[buf][8 + 2 * jj + 1][tid] = *reinterpret_cast<uint32_t*>(&dhi);
        }
    };

    // ---- prologue: tile 0 into buf 0 ----
    pa0 = *reinterpret_cast<const uint4*>(ag);
    pa1 = *reinterpret_cast<const uint4*>(ag + 8);
    cp16(&Bs[0][br0][bc0], bg0);
    cp16(&Bs[0][br1][bc1], bg1);
    asm volatile("cp.async.commit_group;\n" ::: "memory");
    store_a(0, pa0, pa1);

    for (int kt = 0; kt < NKT; kt++) {
        int buf = kt & 1;
        asm volatile("cp.async.wait_group 0;\n" ::: "memory");
        __syncthreads();

        if (kt + 1 < NKT) {
            pa0 = *reinterpret_cast<const uint4*>(ag + (kt + 1) * 16);
            pa1 = *reinterpret_cast<const uint4*>(ag + (kt + 1) * 16 + 8);
            cp16(&Bs[buf ^ 1][br0][bc0], bg0 + (size_t)(kt + 1) * 16 * CTD);
            cp16(&Bs[buf ^ 1][br1][bc1], bg1 + (size_t)(kt + 1) * 16 * CTD);
            asm volatile("cp.async.commit_group;\n" ::: "memory");
        }

#pragma unroll
        for (int k = 0; k < 16; k++) {
            __half2 a2[8], b2[8];
            *reinterpret_cast<uint4*>(&a2[0]) =
                *reinterpret_cast<const uint4*>(&As2[buf][k][ty * 8]);
            *reinterpret_cast<uint4*>(&a2[4]) =
                *reinterpret_cast<const uint4*>(&As2[buf][k][ty * 8 + 4]);
            *reinterpret_cast<uint4*>(&b2[0]) =
                *reinterpret_cast<const uint4*>(&Bs[buf][k][tx * 16]);
            *reinterpret_cast<uint4*>(&b2[4]) =
                *reinterpret_cast<const uint4*>(&Bs[buf][k][tx * 16 + 8]);
#pragma unroll
            for (int i = 0; i < 8; i++)
#pragma unroll
                for (int j = 0; j < 8; j++)
                    acch[i][j] = __hfma2(a2[i], b2[j], acch[i][j]);
        }

        if (kt + 1 < NKT) store_a(buf ^ 1, pa0, pa1);

        if ((kt & 7) == 7 || kt == NKT - 1) {
#pragma unroll
            for (int i = 0; i < 8; i++)
#pragma unroll
                for (int j = 0; j < 8; j++) {
                    float2 t = __half22float2(acch[i][j]);
                    accf[i][j].x += t.x;
                    accf[i][j].y += t.y;
                    acch[i][j] = __half2half2(__ushort_as_half(0));
                }
        }
    }

    // ---- epilogue ----
#pragma unroll
    for (int i = 0; i < 8; i++) {
        int m = m0 + ty * 8 + i;
        int nb = n0 + tx * 16;
#pragma unroll
        for (int jj = 0; jj < 4; jj++) {
            int nn = nb + jj * 4;
            float4 v;
            v.x = accf[i][2 * jj].x;     v.y = accf[i][2 * jj].y;
            v.z = accf[i][2 * jj + 1].x; v.w = accf[i][2 * jj + 1].y;
            if (MODE == 0) {
                if (z < 7) {
                    *reinterpret_cast<uint2*>(
                        g_vh + (size_t)m * (7 * CTD) + (size_t)z * CTD + nn) =
                        f4_to_h4(v);
                } else {
                    float4 bb = *reinterpret_cast<const float4*>(bias + nn);
                    v.x += bb.x; v.y += bb.y; v.z += bb.z; v.w += bb.w;
                    *reinterpret_cast<float4*>(g_vin + (size_t)m * CTD + nn) = v;
                }
            } else {
                float4 bb = *reinterpret_cast<const float4*>(bias + nn);
                float4 vin = *reinterpret_cast<const float4*>(
                    g_vin + (size_t)m * CTD + nn);
                v.x += bb.x + vin.x; v.y += bb.y + vin.y;
                v.z += bb.z + vin.z; v.w += bb.w + vin.w;
                *reinterpret_cast<float4*>(g_vf + (size_t)m * CTD + nn) = v;
            }
        }
    }
}

// ---------------- 3) attention fuse: one warp per (m, head), no barriers ----
__global__ void __launch_bounds__(256) attn_kernel()
{
    int m = blockIdx.x;
    int h = threadIdx.x >> 5;          // warp = head
    int lane = threadIdx.x & 31;
    const __half* vrow = g_vh + (size_t)m * 7 * CTD + h * HDIM + lane * 4;

    // q (slot 0) and kv (slots 1..6): 4 dims per lane as half2x2
    float q[4], kv[6][4];
    {
        uint2 r = *reinterpret_cast<const uint2*>(vrow);
        float2 a = __half22float2(*reinterpret_cast<__half2*>(&r.x));
        float2 b = __half22float2(*reinterpret_cast<__half2*>(&r.y));
        q[0] = a.x * ATT_SCALE; q[1] = a.y * ATT_SCALE;
        q[2] = b.x * ATT_SCALE; q[3] = b.y * ATT_SCALE;
    }
#pragma unroll
    for (int l = 0; l < 6; l++) {
        uint2 r = *reinterpret_cast<const uint2*>(vrow + (size_t)(l + 1) * CTD);
        float2 a = __half22float2(*reinterpret_cast<__half2*>(&r.x));
        float2 b = __half22float2(*reinterpret_cast<__half2*>(&r.y));
        kv[l][0] = a.x; kv[l][1] = a.y; kv[l][2] = b.x; kv[l][3] = b.y;
    }

    float logit[6];
#pragma unroll
    for (int l = 0; l < 6; l++) {
        float p = q[0] * kv[l][0] + q[1] * kv[l][1]
                + q[2] * kv[l][2] + q[3] * kv[l][3];
        logit[l] = warp_sum(p);       // all lanes get the total
    }

    float mx = -1e30f;
#pragma unroll
    for (int l = 0; l < 6; l++) mx = fmaxf(mx, logit[l]);
    float e[6], sum = 0.f;
#pragma unroll
    for (int l = 0; l < 6; l++) { e[l] = expf(logit[l] - mx); sum += e[l]; }
    float inv = 1.0f / sum;

    float f[4] = {0.f, 0.f, 0.f, 0.f};
#pragma unroll
    for (int l = 0; l < 6; l++) {
        float w = e[l] * inv;
#pragma unroll
        for (int d = 0; d < 4; d++) f[d] += w * kv[l][d];
    }

    __half2 lo = __floats2half2_rn(f[0], f[1]);
    __half2 hi = __floats2half2_rn(f[2], f[3]);
    uint2 outv;
    outv.x = *reinterpret_cast<uint32_t*>(&lo);
    outv.y = *reinterpret_cast<uint32_t*>(&hi);
    *reinterpret_cast<uint2*>(
        g_fuse + (size_t)m * CTD + h * HDIM + lane * 4) = outv;
}

// ---------------- 5) per-row cosine ----------------
__global__ void __launch_bounds__(256) cos_kernel(const float* __restrict__ teacher)
{
    int m = blockIdx.x, t = threadIdx.x;
    const float4* a = reinterpret_cast<const float4*>(g_vf + (size_t)m * CTD);
    const float4* b = reinterpret_cast<const float4*>(teacher + (size_t)m * CTD);
    float4 x = a[t], y = b[t];
    float dot = x.x*y.x + x.y*y.y + x.z*y.z + x.w*y.w;
    float n1  = x.x*x.x + x.y*x.y + x.z*x.z + x.w*x.w;
    float n2  = y.x*y.x + y.y*y.y + y.z*y.z + y.w*y.w;

    __shared__ float sd[8], s1[8], s2[8];
    float wd = warp_sum(dot), w1 = warp_sum(n1), w2 = warp_sum(n2);
    int w = t >> 5, lane = t & 31;
    if (lane == 0) { sd[w] = wd; s1[w] = w1; s2[w] = w2; }
    __syncthreads();
    if (t == 0) {
        float td = 0.f, t1 = 0.f, t2 = 0.f;
#pragma unroll
        for (int i = 0; i < 8; i++) { td += sd[i]; t1 += s1[i]; t2 += s2[i]; }
        float na = fmaxf(sqrtf(t1), COS_EPSF);
        float nb = fmaxf(sqrtf(t2), COS_EPSF);
        g_cos[m] = td / (na * nb);
    }
}

// ---------------- 6) final deterministic reduction ----------------
__global__ void __launch_bounds__(512) final_kernel(float* __restrict__ out)
{
    __shared__ float sh[512];
    int t = threadIdx.x;
    float s = 0.f;
    for (int i = t; i < MTOT; i += 512) s += g_cos[i];
    sh[t] = s;
    __syncthreads();
    for (int o = 256; o > 0; o >>= 1) {
        if (t < o) sh[t] += sh[t + o];
        __syncthreads();
    }
    if (t == 0) out[0] = 1.0f - sh[0] / (float)MTOT;
}

// ---------------- launch ----------------
extern "C" void kernel_launch(void* const* d_in, const int* in_sizes, int n_in,
                              void* d_out, int out_size)
{
    const float* features = (const float*)d_in[0];
    const float* teacher  = (const float*)d_in[1];
    const float* ln_scale = (const float*)d_in[2];
    const float* ln_bias  = (const float*)d_in[3];
    const float* w_norm   = (const float*)d_in[4];
    const float* w_in     = (const float*)d_in[5];
    const float* b_in     = (const float*)d_in[6];
    const float* w_out    = (const float*)d_in[7];
    const float* b_out    = (const float*)d_in[8];
    float* out = (float*)d_out;

    size_t total4 = WN4 + WI4 + WO4;
    convert_weights<<<(unsigned)((total4 + 255) / 256), 256>>>(w_norm, w_in, w_out);
    ln_kernel<<<MTOT * 8, 256>>>(features, ln_scale, ln_bias);
    gemm_h2<DIM / 16, 0><<<dim3(CTD / 128, MTOT / 128, 8), 128>>>(b_in);
    attn_kernel<<<MTOT, 256>>>();
    gemm_h2<CTD / 16, 1><<<dim3(CTD / 128, MTOT / 128, 1), 128>>>(b_out);
    cos_kernel<<<MTOT, 256>>>(teacher);
    final_kernel<<<1, 512>>>(out);
}

// round 10
// speedup vs baseline: 1.1108x; 1.0105x over previous
#include <cuda_runtime.h>
#include <cuda_fp16.h>
#include <math.h>
#include <stdint.h>

// ---------------- problem constants ----------------
#define BT      8
#define SEQ     576
#define MTOT    (BT * SEQ)        // 4608
#define NLF     25
#define DIM     2048              // D
#define CTD     1024              // CT
#define HEADS   8
#define HDIM    128
#define ATT_SCALE 0.03125f
#define LN_EPSF   1e-5f
#define COS_EPSF  1e-8f

// ---------------- device scratch ----------------
__device__ __half g_xn[(size_t)8 * MTOT * DIM];   // slots 0..6 LN'd layers, slot 7 raw layer 24
__device__ __half g_wh[(size_t)8 * DIM * CTD];    // slots 0..6 w_norm, slot 7 w_in (fp16)
__device__ __half g_woh[(size_t)CTD * CTD];       // w_out fp16
__device__ __half g_vh[(size_t)MTOT * 7 * CTD];   // vout slots 0..6, fp16
__device__ float  g_vin[(size_t)MTOT * CTD];      // vin fp32
__device__ __half g_fuse[(size_t)MTOT * CTD];
__device__ float  g_vf[(size_t)MTOT * CTD];
__device__ float  g_cos[MTOT];

// ---------------- helpers ----------------
__device__ __forceinline__ float warp_sum(float v) {
#pragma unroll
    for (int o = 16; o > 0; o >>= 1) v += __shfl_xor_sync(0xffffffffu, v, o);
    return v;
}
__device__ __forceinline__ void cp16(void* dst, const void* src) {
    uint32_t d = (uint32_t)__cvta_generic_to_shared(dst);
    asm volatile("cp.async.cg.shared.global [%0], [%1], 16;\n" :: "r"(d), "l"(src));
}
__device__ __forceinline__ uint2 f4_to_h4(float4 v) {
    __half2 lo = __floats2half2_rn(v.x, v.y);
    __half2 hi = __floats2half2_rn(v.z, v.w);
    uint2 r;
    r.x = *reinterpret_cast<uint32_t*>(&lo);
    r.y = *reinterpret_cast<uint32_t*>(&hi);
    return r;
}

// ---------------- 1) fused prep: LN(+copy) and weight conversion ------------
#define WN4 ((size_t)7 * DIM * CTD / 4)
#define WI4 ((size_t)DIM * CTD / 4)
#define WO4 ((size_t)CTD * CTD / 4)
#define LN_BLOCKS (MTOT * 8)
#define CW_TOTAL  (WN4 + WI4 + WO4)
#define CW_BLOCKS ((unsigned)((CW_TOTAL + 255) / 256))

__global__ void __launch_bounds__(256) prep_kernel(
    const float* __restrict__ features,
    const float* __restrict__ ln_scale,
    const float* __restrict__ ln_bias,
    const float* __restrict__ wn,
    const float* __restrict__ wi,
    const float* __restrict__ wo)
{
    if (blockIdx.x >= LN_BLOCKS) {
        size_t i = (size_t)(blockIdx.x - LN_BLOCKS) * 256 + threadIdx.x;
        if (i < WN4) {
            reinterpret_cast<uint2*>(g_wh)[i] =
                f4_to_h4(reinterpret_cast<const float4*>(wn)[i]);
        } else if (i < WN4 + WI4) {
            size_t j = i - WN4;
            reinterpret_cast<uint2*>(g_wh + (size_t)7 * DIM * CTD)[j] =
                f4_to_h4(reinterpret_cast<const float4*>(wi)[j]);
        } else if (i < WN4 + WI4 + WO4) {
            size_t j = i - WN4 - WI4;
            reinterpret_cast<uint2*>(g_woh)[j] =
                f4_to_h4(reinterpret_cast<const float4*>(wo)[j]);
        }
        return;
    }

    int l = blockIdx.x & 7;
    int m = blockIdx.x >> 3;
    int layer = (l < 7) ? (24 - 4 * l) : 24;
    const float4* x = reinterpret_cast<const float4*>(
        features + ((size_t)m * NLF + layer) * DIM);
    int t = threadIdx.x;

    float4 a = x[t];
    float4 b = x[t + 256];
    uint2* o = reinterpret_cast<uint2*>(g_xn + ((size_t)l * MTOT + m) * DIM);

    if (l == 7) {
        o[t] = f4_to_h4(a);
        o[t + 256] = f4_to_h4(b);
        return;
    }

    float s  = a.x + a.y + a.z + a.w + b.x + b.y + b.z + b.w;
    float ss = a.x*a.x + a.y*a.y + a.z*a.z + a.w*a.w
             + b.x*b.x + b.y*b.y + b.z*b.z + b.w*b.w;

    __shared__ float shs[8], shss[8];
    float ws  = warp_sum(s);
    float wss = warp_sum(ss);
    int w = t >> 5, lane = t & 31;
    if (lane == 0) { shs[w] = ws; shss[w] = wss; }
    __syncthreads();
    float tot = 0.f, tot2 = 0.f;
#pragma unroll
    for (int i = 0; i < 8; i++) { tot += shs[i]; tot2 += shss[i]; }

    float mu  = tot * (1.0f / DIM);
    float var = tot2 * (1.0f / DIM) - mu * mu;
    float rs  = rsqrtf(var + LN_EPSF);

    const float4* sc = reinterpret_cast<const float4*>(ln_scale + (size_t)l * DIM);
    const float4* bi = reinterpret_cast<const float4*>(ln_bias  + (size_t)l * DIM);
    float4 s0 = sc[t],       b0 = bi[t];
    float4 s1 = sc[t + 256], b1 = bi[t + 256];
    float4 o0, o1;
    o0.x = (a.x - mu) * rs * s0.x + b0.x;
    o0.y = (a.y - mu) * rs * s0.y + b0.y;
    o0.z = (a.z - mu) * rs * s0.z + b0.z;
    o0.w = (a.w - mu) * rs * s0.w + b0.w;
    o1.x = (b.x - mu) * rs * s1.x + b1.x;
    o1.y = (b.y - mu) * rs * s1.y + b1.y;
    o1.z = (b.z - mu) * rs * s1.z + b1.z;
    o1.w = (b.w - mu) * rs * s1.w + b1.w;
    o[t] = f4_to_h4(o0);
    o[t + 256] = f4_to_h4(o1);
}

// ---------------- 2) HFMA2 GEMM v4: 128x128x16, 256 thr, 8Mx8N/thread -------
// 2 CTAs/SM (128-reg cap), 16 warps/SM -> 4 warps/SMSP.
// A dup (v,v) half2 pairs in smem; B fp16 [K,N] natural via cp.async.
// half2 accumulators flushed to fp32 regs every 8 K-tiles (K=128 window).
// MODE 0: g_xn[z] @ g_wh[z] -> z<7: g_vh slot z (fp16); z==7: g_vin + b_in
// MODE 1: g_fuse @ g_woh + vin + b_out -> g_vf
template<int NKT, int MODE>
__global__ void __launch_bounds__(256, 2) gemm_h4(
    const float* __restrict__ bias)
{
    __shared__ __align__(16) uint32_t As2[2][16][128];  // dup half2 pairs, 16 KB
    __shared__ __align__(16) __half   Bs[2][16][128];   // 8 KB

    int tid = threadIdx.x;
    int m0 = blockIdx.y * 128, n0 = blockIdx.x * 128;
    int z = (MODE == 0) ? blockIdx.z : 0;

    const __half* A;
    const __half* B;
    if (MODE == 0) {
        A = g_xn + (size_t)z * MTOT * DIM;
        B = g_wh + (size_t)z * DIM * CTD;
    } else {
        A = g_fuse;
        B = g_woh;
    }
    const int lda = (MODE == 0) ? DIM : CTD;

    // A loader: thread t -> row t>>1, col (t&1)*8 (one uint4 per tile)
    int arow = tid >> 1, acol = (tid & 1) * 8;
    const __half* ag = A + (size_t)(m0 + arow) * lda + acol;
    // B loader: thread t -> krow t>>4, col (t&15)*8 (one cp16 per tile)
    int brow = tid >> 4, bcol = (tid & 15) * 8;
    const __half* bg = B + (size_t)brow * CTD + n0 + bcol;

    // compute mapping: ty 0..15 (8 m-rows), tx 0..15 (8 n-cols)
    int ty = tid >> 4, tx = tid & 15;

    float2  accf[8][4];
    __half2 acch[8][4];
#pragma unroll
    for (int i = 0; i < 8; i++)
#pragma unroll
        for (int j = 0; j < 4; j++) {
            accf[i][j] = make_float2(0.f, 0.f);
            acch[i][j] = __half2half2(__ushort_as_half(0));
        }

    uint4 pa;

    auto store_a = [&](int buf) {
        const __half2* hp = reinterpret_cast<const __half2*>(&pa);
#pragma unroll
        for (int jj = 0; jj < 4; jj++) {
            __half2 dlo = __half2half2(__low2half(hp[jj]));
            __half2 dhi = __half2half2(__high2half(hp[jj]));
            As2[buf][acol + 2 * jj][arow]     = *reinterpret_cast<uint32_t*>(&dlo);
            As2[buf][acol + 2 * jj + 1][arow] = *reinterpret_cast<uint32_t*>(&dhi);
        }
    };

    // ---- prologue: tile 0 into buf 0 ----
    pa = *reinterpret_cast<const uint4*>(ag);
    cp16(&Bs[0][brow][bcol], bg);
    asm volatile("cp.async.commit_group;\n" ::: "memory");
    store_a(0);

    for (int kt = 0; kt < NKT; kt++) {
        int buf = kt & 1;
        asm volatile("cp.async.wait_group 0;\n" ::: "memory");
        __syncthreads();

        if (kt + 1 < NKT) {
            pa = *reinterpret_cast<const uint4*>(ag + (kt + 1) * 16);
            cp16(&Bs[buf ^ 1][brow][bcol], bg + (size_t)(kt + 1) * 16 * CTD);
            asm volatile("cp.async.commit_group;\n" ::: "memory");
        }

#pragma unroll
        for (int k = 0; k < 16; k++) {
            __half2 a2[8], b2[4];
            *reinterpret_cast<uint4*>(&a2[0]) =
                *reinterpret_cast<const uint4*>(&As2[buf][k][ty * 8]);
            *reinterpret_cast<uint4*>(&a2[4]) =
                *reinterpret_cast<const uint4*>(&As2[buf][k][ty * 8 + 4]);
            *reinterpret_cast<uint4*>(&b2[0]) =
                *reinterpret_cast<const uint4*>(&Bs[buf][k][tx * 8]);
#pragma unroll
            for (int i = 0; i < 8; i++)
#pragma unroll
                for (int j = 0; j < 4; j++)
                    acch[i][j] = __hfma2(a2[i], b2[j], acch[i][j]);
        }

        if (kt + 1 < NKT) store_a(buf ^ 1);

        if ((kt & 7) == 7 || kt == NKT - 1) {
#pragma unroll
            for (int i = 0; i < 8; i++)
#pragma unroll
                for (int j = 0; j < 4; j++) {
                    float2 t = __half22float2(acch[i][j]);
                    accf[i][j].x += t.x;
                    accf[i][j].y += t.y;
                    acch[i][j] = __half2half2(__ushort_as_half(0));
                }
        }
    }

    // ---- epilogue: 8 rows x 8 cols per thread ----
#pragma unroll
    for (int i = 0; i < 8; i++) {
        int m = m0 + ty * 8 + i;
        int n = n0 + tx * 8;
        float4 v0, v1;
        v0.x = accf[i][0].x; v0.y = accf[i][0].y;
        v0.z = accf[i][1].x; v0.w = accf[i][1].y;
        v1.x = accf[i][2].x; v1.y = accf[i][2].y;
        v1.z = accf[i][3].x; v1.w = accf[i][3].y;
        if (MODE == 0) {
            if (z < 7) {
                uint2 h0 = f4_to_h4(v0);
                uint2 h1 = f4_to_h4(v1);
                uint4 hv = make_uint4(h0.x, h0.y, h1.x, h1.y);
                *reinterpret_cast<uint4*>(
                    g_vh + (size_t)m * (7 * CTD) + (size_t)z * CTD + n) = hv;
            } else {
                float4 b0 = *reinterpret_cast<const float4*>(bias + n);
                float4 b1 = *reinterpret_cast<const float4*>(bias + n + 4);
                v0.x += b0.x; v0.y += b0.y; v0.z += b0.z; v0.w += b0.w;
                v1.x += b1.x; v1.y += b1.y; v1.z += b1.z; v1.w += b1.w;
                float* dst = g_vin + (size_t)m * CTD + n;
                *reinterpret_cast<float4*>(dst)     = v0;
                *reinterpret_cast<float4*>(dst + 4) = v1;
            }
        } else {
            float4 b0 = *reinterpret_cast<const float4*>(bias + n);
            float4 b1 = *reinterpret_cast<const float4*>(bias + n + 4);
            const float* vin = g_vin + (size_t)m * CTD + n;
            float4 i0 = *reinterpret_cast<const float4*>(vin);
            float4 i1 = *reinterpret_cast<const float4*>(vin + 4);
            v0.x += b0.x + i0.x; v0.y += b0.y + i0.y;
            v0.z += b0.z + i0.z; v0.w += b0.w + i0.w;
            v1.x += b1.x + i1.x; v1.y += b1.y + i1.y;
            v1.z += b1.z + i1.z; v1.w += b1.w + i1.w;
            float* dst = g_vf + (size_t)m * CTD + n;
            *reinterpret_cast<float4*>(dst)     = v0;
            *reinterpret_cast<float4*>(dst + 4) = v1;
        }
    }
}

// ---------------- 3) attention fuse: one warp per (m, head) ----------------
__global__ void __launch_bounds__(256) attn_kernel()
{
    int m = blockIdx.x;
    int h = threadIdx.x >> 5;
    int lane = threadIdx.x & 31;
    const __half* vrow = g_vh + (size_t)m * 7 * CTD + h * HDIM + lane * 4;

    float q[4], kv[6][4];
    {
        uint2 r = *reinterpret_cast<const uint2*>(vrow);
        float2 a = __half22float2(*reinterpret_cast<__half2*>(&r.x));
        float2 b = __half22float2(*reinterpret_cast<__half2*>(&r.y));
        q[0] = a.x * ATT_SCALE; q[1] = a.y * ATT_SCALE;
        q[2] = b.x * ATT_SCALE; q[3] = b.y * ATT_SCALE;
    }
#pragma unroll
    for (int l = 0; l < 6; l++) {
        uint2 r = *reinterpret_cast<const uint2*>(vrow + (size_t)(l + 1) * CTD);
        float2 a = __half22float2(*reinterpret_cast<__half2*>(&r.x));
        float2 b = __half22float2(*reinterpret_cast<__half2*>(&r.y));
        kv[l][0] = a.x; kv[l][1] = a.y; kv[l][2] = b.x; kv[l][3] = b.y;
    }

    float logit[6];
#pragma unroll
    for (int l = 0; l < 6; l++) {
        float p = q[0] * kv[l][0] + q[1] * kv[l][1]
                + q[2] * kv[l][2] + q[3] * kv[l][3];
        logit[l] = warp_sum(p);
    }

    float mx = -1e30f;
#pragma unroll
    for (int l = 0; l < 6; l++) mx = fmaxf(mx, logit[l]);
    float e[6], sum = 0.f;
#pragma unroll
    for (int l = 0; l < 6; l++) { e[l] = expf(logit[l] - mx); sum += e[l]; }
    float inv = 1.0f / sum;

    float f[4] = {0.f, 0.f, 0.f, 0.f};
#pragma unroll
    for (int l = 0; l < 6; l++) {
        float w = e[l] * inv;
#pragma unroll
        for (int d = 0; d < 4; d++) f[d] += w * kv[l][d];
    }

    __half2 lo = __floats2half2_rn(f[0], f[1]);
    __half2 hi = __floats2half2_rn(f[2], f[3]);
    uint2 outv;
    outv.x = *reinterpret_cast<uint32_t*>(&lo);
    outv.y = *reinterpret_cast<uint32_t*>(&hi);
    *reinterpret_cast<uint2*>(
        g_fuse + (size_t)m * CTD + h * HDIM + lane * 4) = outv;
}

// ---------------- 5) per-row cosine ----------------
__global__ void __launch_bounds__(256) cos_kernel(const float* __restrict__ teacher)
{
    int m = blockIdx.x, t = threadIdx.x;
    const float4* a = reinterpret_cast<const float4*>(g_vf + (size_t)m * CTD);
    const float4* b = reinterpret_cast<const float4*>(teacher + (size_t)m * CTD);
    float4 x = a[t], y = b[t];
    float dot = x.x*y.x + x.y*y.y + x.z*y.z + x.w*y.w;
    float n1  = x.x*x.x + x.y*x.y + x.z*x.z + x.w*x.w;
    float n2  = y.x*y.x + y.y*y.y + y.z*y.z + y.w*y.w;

    __shared__ float sd[8], s1[8], s2[8];
    float wd = warp_sum(dot), w1 = warp_sum(n1), w2 = warp_sum(n2);
    int w = t >> 5, lane = t & 31;
    if (lane == 0) { sd[w] = wd; s1[w] = w1; s2[w] = w2; }
    __syncthreads();
    if (t == 0) {
        float td = 0.f, t1 = 0.f, t2 = 0.f;
#pragma unroll
        for (int i = 0; i < 8; i++) { td += sd[i]; t1 += s1[i]; t2 += s2[i]; }
        float na = fmaxf(sqrtf(t1), COS_EPSF);
        float nb = fmaxf(sqrtf(t2), COS_EPSF);
        g_cos[m] = td / (na * nb);
    }
}

// ---------------- 6) final deterministic reduction ----------------
__global__ void __launch_bounds__(512) final_kernel(float* __restrict__ out)
{
    __shared__ float sh[512];
    int t = threadIdx.x;
    float s = 0.f;
    for (int i = t; i < MTOT; i += 512) s += g_cos[i];
    sh[t] = s;
    __syncthreads();
    for (int o = 256; o > 0; o >>= 1) {
        if (t < o) sh[t] += sh[t + o];
        __syncthreads();
    }
    if (t == 0) out[0] = 1.0f - sh[0] / (float)MTOT;
}

// ---------------- launch ----------------
extern "C" void kernel_launch(void* const* d_in, const int* in_sizes, int n_in,
                              void* d_out, int out_size)
{
    const float* features = (const float*)d_in[0];
    const float* teacher  = (const float*)d_in[1];
    const float* ln_scale = (const float*)d_in[2];
    const float* ln_bias  = (const float*)d_in[3];
    const float* w_norm   = (const float*)d_in[4];
    const float* w_in     = (const float*)d_in[5];
    const float* b_in     = (const float*)d_in[6];
    const float* w_out    = (const float*)d_in[7];
    const float* b_out    = (const float*)d_in[8];
    float* out = (float*)d_out;

    prep_kernel<<<LN_BLOCKS + CW_BLOCKS, 256>>>(
        features, ln_scale, ln_bias, w_norm, w_in, w_out);
    gemm_h4<DIM / 16, 0><<<dim3(CTD / 128, MTOT / 128, 8), 256>>>(b_in);
    attn_kernel<<<MTOT, 256>>>();
    gemm_h4<CTD / 16, 1><<<dim3(CTD / 128, MTOT / 128, 1), 256>>>(b_out);
    cos_kernel<<<MTOT, 256>>>(teacher);
    final_kernel<<<1, 512>>>(out);
}

// round 11
// speedup vs baseline: 1.1141x; 1.0030x over previous
#include <cuda_runtime.h>
#include <cuda_fp16.h>
#include <math.h>
#include <stdint.h>

// ---------------- problem constants ----------------
#define BT      8
#define SEQ     576
#define MTOT    (BT * SEQ)        // 4608
#define NLF     25
#define DIM     2048              // D
#define CTD     1024              // CT
#define HEADS   8
#define HDIM    128
#define ATT_SCALE 0.03125f
#define LN_EPSF   1e-5f
#define COS_EPSF  1e-8f

// ---------------- device scratch ----------------
__device__ __half g_xn[(size_t)8 * MTOT * DIM];   // slots 0..6 LN'd layers, slot 7 raw layer 24
__device__ __half g_wh[(size_t)8 * DIM * CTD];    // slots 0..6 w_norm, slot 7 w_in (fp16)
__device__ __half g_woh[(size_t)CTD * CTD];       // w_out fp16
__device__ __half g_vh[(size_t)MTOT * 7 * CTD];   // vout slots 0..6, fp16
__device__ float  g_vin[(size_t)MTOT * CTD];      // vin fp32
__device__ __half g_fuse[(size_t)MTOT * CTD];
__device__ float  g_vf[(size_t)MTOT * CTD];
__device__ float  g_cos[MTOT];

// ---------------- helpers ----------------
__device__ __forceinline__ float warp_sum(float v) {
#pragma unroll
    for (int o = 16; o > 0; o >>= 1) v += __shfl_xor_sync(0xffffffffu, v, o);
    return v;
}
__device__ __forceinline__ void cp16(void* dst, const void* src) {
    uint32_t d = (uint32_t)__cvta_generic_to_shared(dst);
    asm volatile("cp.async.cg.shared.global [%0], [%1], 16;\n" :: "r"(d), "l"(src));
}
__device__ __forceinline__ uint2 f4_to_h4(float4 v) {
    __half2 lo = __floats2half2_rn(v.x, v.y);
    __half2 hi = __floats2half2_rn(v.z, v.w);
    uint2 r;
    r.x = *reinterpret_cast<uint32_t*>(&lo);
    r.y = *reinterpret_cast<uint32_t*>(&hi);
    return r;
}

// ---------------- 1) fused prep: LN(+copy) and weight conversion ------------
#define WN4 ((size_t)7 * DIM * CTD / 4)
#define WI4 ((size_t)DIM * CTD / 4)
#define WO4 ((size_t)CTD * CTD / 4)
#define LN_BLOCKS (MTOT * 8)
#define CW_TOTAL  (WN4 + WI4 + WO4)
#define CW_BLOCKS ((unsigned)((CW_TOTAL + 255) / 256))

__global__ void __launch_bounds__(256) prep_kernel(
    const float* __restrict__ features,
    const float* __restrict__ ln_scale,
    const float* __restrict__ ln_bias,
    const float* __restrict__ wn,
    const float* __restrict__ wi,
    const float* __restrict__ wo)
{
    if (blockIdx.x >= LN_BLOCKS) {
        size_t i = (size_t)(blockIdx.x - LN_BLOCKS) * 256 + threadIdx.x;
        if (i < WN4) {
            reinterpret_cast<uint2*>(g_wh)[i] =
                f4_to_h4(reinterpret_cast<const float4*>(wn)[i]);
        } else if (i < WN4 + WI4) {
            size_t j = i - WN4;
            reinterpret_cast<uint2*>(g_wh + (size_t)7 * DIM * CTD)[j] =
                f4_to_h4(reinterpret_cast<const float4*>(wi)[j]);
        } else if (i < WN4 + WI4 + WO4) {
            size_t j = i - WN4 - WI4;
            reinterpret_cast<uint2*>(g_woh)[j] =
                f4_to_h4(reinterpret_cast<const float4*>(wo)[j]);
        }
        return;
    }

    int l = blockIdx.x & 7;
    int m = blockIdx.x >> 3;
    int layer = (l < 7) ? (24 - 4 * l) : 24;
    const float4* x = reinterpret_cast<const float4*>(
        features + ((size_t)m * NLF + layer) * DIM);
    int t = threadIdx.x;

    float4 a = x[t];
    float4 b = x[t + 256];
    uint2* o = reinterpret_cast<uint2*>(g_xn + ((size_t)l * MTOT + m) * DIM);

    if (l == 7) {
        o[t] = f4_to_h4(a);
        o[t + 256] = f4_to_h4(b);
        return;
    }

    float s  = a.x + a.y + a.z + a.w + b.x + b.y + b.z + b.w;
    float ss = a.x*a.x + a.y*a.y + a.z*a.z + a.w*a.w
             + b.x*b.x + b.y*b.y + b.z*b.z + b.w*b.w;

    __shared__ float shs[8], shss[8];
    float ws  = warp_sum(s);
    float wss = warp_sum(ss);
    int w = t >> 5, lane = t & 31;
    if (lane == 0) { shs[w] = ws; shss[w] = wss; }
    __syncthreads();
    float tot = 0.f, tot2 = 0.f;
#pragma unroll
    for (int i = 0; i < 8; i++) { tot += shs[i]; tot2 += shss[i]; }

    float mu  = tot * (1.0f / DIM);
    float var = tot2 * (1.0f / DIM) - mu * mu;
    float rs  = rsqrtf(var + LN_EPSF);

    const float4* sc = reinterpret_cast<const float4*>(ln_scale + (size_t)l * DIM);
    const float4* bi = reinterpret_cast<const float4*>(ln_bias  + (size_t)l * DIM);
    float4 s0 = sc[t],       b0 = bi[t];
    float4 s1 = sc[t + 256], b1 = bi[t + 256];
    float4 o0, o1;
    o0.x = (a.x - mu) * rs * s0.x + b0.x;
    o0.y = (a.y - mu) * rs * s0.y + b0.y;
    o0.z = (a.z - mu) * rs * s0.z + b0.z;
    o0.w = (a.w - mu) * rs * s0.w + b0.w;
    o1.x = (b.x - mu) * rs * s1.x + b1.x;
    o1.y = (b.y - mu) * rs * s1.y + b1.y;
    o1.z = (b.z - mu) * rs * s1.z + b1.z;
    o1.w = (b.w - mu) * rs * s1.w + b1.w;
    o[t] = f4_to_h4(o0);
    o[t + 256] = f4_to_h4(o1);
}

// ---------------- 2) HFMA2 GEMM v5: 128x128x32 tile, 256 thr, 8Mx8N/thread --
// Identical geometry to v4 except K-tile 32 (halved barrier frequency).
// 2 CTAs/SM. A dup (v,v) half2 pairs in smem; B fp16 [K,N] natural via cp.async.
// half2 accumulators flushed to fp32 regs every 4 K-tiles (K=128 window).
// MODE 0: g_xn[z] @ g_wh[z] -> z<7: g_vh slot z (fp16); z==7: g_vin + b_in
// MODE 1: g_fuse @ g_woh + vin + b_out -> g_vf
#define KT 32
template<int NKT, int MODE>
__global__ void __launch_bounds__(256, 2) gemm_h5(
    const float* __restrict__ bias)
{
    __shared__ __align__(16) uint32_t As2[2][KT][128];  // dup half2 pairs, 32 KB
    __shared__ __align__(16) __half   Bs[2][KT][128];   // 16 KB

    int tid = threadIdx.x;
    int m0 = blockIdx.y * 128, n0 = blockIdx.x * 128;
    int z = (MODE == 0) ? blockIdx.z : 0;

    const __half* A;
    const __half* B;
    if (MODE == 0) {
        A = g_xn + (size_t)z * MTOT * DIM;
        B = g_wh + (size_t)z * DIM * CTD;
    } else {
        A = g_fuse;
        B = g_woh;
    }
    const int lda = (MODE == 0) ? DIM : CTD;

    // A loader: thread t -> row t>>1, k-cols (t&1)*16 .. +15 (two uint4)
    int arow = tid >> 1, acol = (tid & 1) * 16;
    const __half* ag = A + (size_t)(m0 + arow) * lda + acol;
    // B loader: thread t -> krow t>>3, cols (t&7)*16 .. +15 (two cp16)
    int brow = tid >> 3, bcol = (tid & 7) * 16;
    const __half* bg = B + (size_t)brow * CTD + n0 + bcol;

    // compute mapping: ty 0..15 (8 m-rows), tx 0..15 (8 n-cols)
    int ty = tid >> 4, tx = tid & 15;

    float2  accf[8][4];
    __half2 acch[8][4];
#pragma unroll
    for (int i = 0; i < 8; i++)
#pragma unroll
        for (int j = 0; j < 4; j++) {
            accf[i][j] = make_float2(0.f, 0.f);
            acch[i][j] = __half2half2(__ushort_as_half(0));
        }

    uint4 pa0, pa1;

    auto store_a = [&](int buf) {
        const __half2* h0 = reinterpret_cast<const __half2*>(&pa0);
        const __half2* h1 = reinterpret_cast<const __half2*>(&pa1);
#pragma unroll
        for (int jj = 0; jj < 4; jj++) {
            __half2 dlo = __half2half2(__low2half(h0[jj]));
            __half2 dhi = __half2half2(__high2half(h0[jj]));
            As2[buf][acol + 2 * jj][arow]     = *reinterpret_cast<uint32_t*>(&dlo);
            As2[buf][acol + 2 * jj + 1][arow] = *reinterpret_cast<uint32_t*>(&dhi);
        }
#pragma unroll
        for (int jj = 0; jj < 4; jj++) {
            __half2 dlo = __half2half2(__low2half(h1[jj]));
            __half2 dhi = __half2half2(__high2half(h1[jj]));
            As2[buf][acol + 8 + 2 * jj][arow]     = *reinterpret_cast<uint32_t*>(&dlo);
            As2[buf][acol + 8 + 2 * jj + 1][arow] = *reinterpret_cast<uint32_t*>(&dhi);
        }
    };

    // ---- prologue: tile 0 into buf 0 ----
    pa0 = *reinterpret_cast<const uint4*>(ag);
    pa1 = *reinterpret_cast<const uint4*>(ag + 8);
    cp16(&Bs[0][brow][bcol], bg);
    cp16(&Bs[0][brow][bcol + 8], bg + 8);
    asm volatile("cp.async.commit_group;\n" ::: "memory");
    store_a(0);

    for (int kt = 0; kt < NKT; kt++) {
        int buf = kt & 1;
        asm volatile("cp.async.wait_group 0;\n" ::: "memory");
        __syncthreads();

        if (kt + 1 < NKT) {
            pa0 = *reinterpret_cast<const uint4*>(ag + (kt + 1) * KT);
            pa1 = *reinterpret_cast<const uint4*>(ag + (kt + 1) * KT + 8);
            const __half* bn = bg + (size_t)(kt + 1) * KT * CTD;
            cp16(&Bs[buf ^ 1][brow][bcol], bn);
            cp16(&Bs[buf ^ 1][brow][bcol + 8], bn + 8);
            asm volatile("cp.async.commit_group;\n" ::: "memory");
        }

#pragma unroll
        for (int k = 0; k < KT; k++) {
            __half2 a2[8], b2[4];
            *reinterpret_cast<uint4*>(&a2[0]) =
                *reinterpret_cast<const uint4*>(&As2[buf][k][ty * 8]);
            *reinterpret_cast<uint4*>(&a2[4]) =
                *reinterpret_cast<const uint4*>(&As2[buf][k][ty * 8 + 4]);
            *reinterpret_cast<uint4*>(&b2[0]) =
                *reinterpret_cast<const uint4*>(&Bs[buf][k][tx * 8]);
#pragma unroll
            for (int i = 0; i < 8; i++)
#pragma unroll
                for (int j = 0; j < 4; j++)
                    acch[i][j] = __hfma2(a2[i], b2[j], acch[i][j]);
        }

        if (kt + 1 < NKT) store_a(buf ^ 1);

        if ((kt & 3) == 3 || kt == NKT - 1) {
#pragma unroll
            for (int i = 0; i < 8; i++)
#pragma unroll
                for (int j = 0; j < 4; j++) {
                    float2 t = __half22float2(acch[i][j]);
                    accf[i][j].x += t.x;
                    accf[i][j].y += t.y;
                    acch[i][j] = __half2half2(__ushort_as_half(0));
                }
        }
    }

    // ---- epilogue: 8 rows x 8 cols per thread ----
#pragma unroll
    for (int i = 0; i < 8; i++) {
        int m = m0 + ty * 8 + i;
        int n = n0 + tx * 8;
        float4 v0, v1;
        v0.x = accf[i][0].x; v0.y = accf[i][0].y;
        v0.z = accf[i][1].x; v0.w = accf[i][1].y;
        v1.x = accf[i][2].x; v1.y = accf[i][2].y;
        v1.z = accf[i][3].x; v1.w = accf[i][3].y;
        if (MODE == 0) {
            if (z < 7) {
                uint2 h0 = f4_to_h4(v0);
                uint2 h1 = f4_to_h4(v1);
                uint4 hv = make_uint4(h0.x, h0.y, h1.x, h1.y);
                *reinterpret_cast<uint4*>(
                    g_vh + (size_t)m * (7 * CTD) + (size_t)z * CTD + n) = hv;
            } else {
                float4 b0 = *reinterpret_cast<const float4*>(bias + n);
                float4 b1 = *reinterpret_cast<const float4*>(bias + n + 4);
                v0.x += b0.x; v0.y += b0.y; v0.z += b0.z; v0.w += b0.w;
                v1.x += b1.x; v1.y += b1.y; v1.z += b1.z; v1.w += b1.w;
                float* dst = g_vin + (size_t)m * CTD + n;
                *reinterpret_cast<float4*>(dst)     = v0;
                *reinterpret_cast<float4*>(dst + 4) = v1;
            }
        } else {
            float4 b0 = *reinterpret_cast<const float4*>(bias + n);
            float4 b1 = *reinterpret_cast<const float4*>(bias + n + 4);
            const float* vin = g_vin + (size_t)m * CTD + n;
            float4 i0 = *reinterpret_cast<const float4*>(vin);
            float4 i1 = *reinterpret_cast<const float4*>(vin + 4);
            v0.x += b0.x + i0.x; v0.y += b0.y + i0.y;
            v0.z += b0.z + i0.z; v0.w += b0.w + i0.w;
            v1.x += b1.x + i1.x; v1.y += b1.y + i1.y;
            v1.z += b1.z + i1.z; v1.w += b1.w + i1.w;
            float* dst = g_vf + (size_t)m * CTD + n;
            *reinterpret_cast<float4*>(dst)     = v0;
            *reinterpret_cast<float4*>(dst + 4) = v1;
        }
    }
}

// ---------------- 3) attention fuse: one warp per (m, head) ----------------
__global__ void __launch_bounds__(256) attn_kernel()
{
    int m = blockIdx.x;
    int h = threadIdx.x >> 5;
    int lane = threadIdx.x & 31;
    const __half* vrow = g_vh + (size_t)m * 7 * CTD + h * HDIM + lane * 4;

    float q[4], kv[6][4];
    {
        uint2 r = *reinterpret_cast<const uint2*>(vrow);
        float2 a = __half22float2(*reinterpret_cast<__half2*>(&r.x));
        float2 b = __half22float2(*reinterpret_cast<__half2*>(&r.y));
        q[0] = a.x * ATT_SCALE; q[1] = a.y * ATT_SCALE;
        q[2] = b.x * ATT_SCALE; q[3] = b.y * ATT_SCALE;
    }
#pragma unroll
    for (int l = 0; l < 6; l++) {
        uint2 r = *reinterpret_cast<const uint2*>(vrow + (size_t)(l + 1) * CTD);
        float2 a = __half22float2(*reinterpret_cast<__half2*>(&r.x));
        float2 b = __half22float2(*reinterpret_cast<__half2*>(&r.y));
        kv[l][0] = a.x; kv[l][1] = a.y; kv[l][2] = b.x; kv[l][3] = b.y;
    }

    float logit[6];
#pragma unroll
    for (int l = 0; l < 6; l++) {
        float p = q[0] * kv[l][0] + q[1] * kv[l][1]
                + q[2] * kv[l][2] + q[3] * kv[l][3];
        logit[l] = warp_sum(p);
    }

    float mx = -1e30f;
#pragma unroll
    for (int l = 0; l < 6; l++) mx = fmaxf(mx, logit[l]);
    float e[6], sum = 0.f;
#pragma unroll
    for (int l = 0; l < 6; l++) { e[l] = expf(logit[l] - mx); sum += e[l]; }
    float inv = 1.0f / sum;

    float f[4] = {0.f, 0.f, 0.f, 0.f};
#pragma unroll
    for (int l = 0; l < 6; l++) {
        float w = e[l] * inv;
#pragma unroll
        for (int d = 0; d < 4; d++) f[d] += w * kv[l][d];
    }

    __half2 lo = __floats2half2_rn(f[0], f[1]);
    __half2 hi = __floats2half2_rn(f[2], f[3]);
    uint2 outv;
    outv.x = *reinterpret_cast<uint32_t*>(&lo);
    outv.y = *reinterpret_cast<uint32_t*>(&hi);
    *reinterpret_cast<uint2*>(
        g_fuse + (size_t)m * CTD + h * HDIM + lane * 4) = outv;
}

// ---------------- 5) per-row cosine ----------------
__global__ void __launch_bounds__(256) cos_kernel(const float* __restrict__ teacher)
{
    int m = blockIdx.x, t = threadIdx.x;
    const float4* a = reinterpret_cast<const float4*>(g_vf + (size_t)m * CTD);
    const float4* b = reinterpret_cast<const float4*>(teacher + (size_t)m * CTD);
    float4 x = a[t], y = b[t];
    float dot = x.x*y.x + x.y*y.y + x.z*y.z + x.w*y.w;
    float n1  = x.x*x.x + x.y*x.y + x.z*x.z + x.w*x.w;
    float n2  = y.x*y.x + y.y*y.y + y.z*y.z + y.w*y.w;

    __shared__ float sd[8], s1[8], s2[8];
    float wd = warp_sum(dot), w1 = warp_sum(n1), w2 = warp_sum(n2);
    int w = t >> 5, lane = t & 31;
    if (lane == 0) { sd[w] = wd; s1[w] = w1; s2[w] = w2; }
    __syncthreads();
    if (t == 0) {
        float td = 0.f, t1 = 0.f, t2 = 0.f;
#pragma unroll
        for (int i = 0; i < 8; i++) { td += sd[i]; t1 += s1[i]; t2 += s2[i]; }
        float na = fmaxf(sqrtf(t1), COS_EPSF);
        float nb = fmaxf(sqrtf(t2), COS_EPSF);
        g_cos[m] = td / (na * nb);
    }
}

// ---------------- 6) final deterministic reduction ----------------
__global__ void __launch_bounds__(512) final_kernel(float* __restrict__ out)
{
    __shared__ float sh[512];
    int t = threadIdx.x;
    float s = 0.f;
    for (int i = t; i < MTOT; i += 512) s += g_cos[i];
    sh[t] = s;
    __syncthreads();
    for (int o = 256; o > 0; o >>= 1) {
        if (t < o) sh[t] += sh[t + o];
        __syncthreads();
    }
    if (t == 0) out[0] = 1.0f - sh[0] / (float)MTOT;
}

// ---------------- launch ----------------
extern "C" void kernel_launch(void* const* d_in, const int* in_sizes, int n_in,
                              void* d_out, int out_size)
{
    const float* features = (const float*)d_in[0];
    const float* teacher  = (const float*)d_in[1];
    const float* ln_scale = (const float*)d_in[2];
    const float* ln_bias  = (const float*)d_in[3];
    const float* w_norm   = (const float*)d_in[4];
    const float* w_in     = (const float*)d_in[5];
    const float* b_in     = (const float*)d_in[6];
    const float* w_out    = (const float*)d_in[7];
    const float* b_out    = (const float*)d_in[8];
    float* out = (float*)d_out;

    prep_kernel<<<LN_BLOCKS + CW_BLOCKS, 256>>>(
        features, ln_scale, ln_bias, w_norm, w_in, w_out);
    gemm_h5<DIM / KT, 0><<<dim3(CTD / 128, MTOT / 128, 8), 256>>>(b_in);
    attn_kernel<<<MTOT, 256>>>();
    gemm_h5<CTD / KT, 1><<<dim3(CTD / 128, MTOT / 128, 1), 256>>>(b_out);
    cos_kernel<<<MTOT, 256>>>(teacher);
    final_kernel<<<1, 512>>>(out);
}

// round 12
// speedup vs baseline: 1.1197x; 1.0050x over previous
#include <cuda_runtime.h>
#include <cuda_fp16.h>
#include <math.h>
#include <stdint.h>

// ---------------- problem constants ----------------
#define BT      8
#define SEQ     576
#define MTOT    (BT * SEQ)        // 4608
#define NLF     25
#define DIM     2048              // D
#define CTD     1024              // CT
#define HEADS   8
#define HDIM    128
#define ATT_SCALE 0.03125f
#define LN_EPSF   1e-5f
#define COS_EPSF  1e-8f

// ---------------- device scratch ----------------
__device__ __half g_xn[(size_t)8 * MTOT * DIM];   // slots 0..6 LN'd layers, slot 7 raw layer 24
__device__ __half g_wh[(size_t)8 * DIM * CTD];    // slots 0..6 w_norm, slot 7 w_in (fp16)
__device__ __half g_woh[(size_t)CTD * CTD];       // w_out fp16
__device__ __half g_vh[(size_t)MTOT * 7 * CTD];   // vout slots 0..6, fp16
__device__ float  g_vin[(size_t)MTOT * CTD];      // vin fp32
__device__ __half g_fuse[(size_t)MTOT * CTD];
__device__ float  g_part[(size_t)8 * MTOT * 2];   // per-strip (dot, n1) partials
__device__ float  g_n2[MTOT];                     // teacher squared norms

// ---------------- helpers ----------------
__device__ __forceinline__ float warp_sum(float v) {
#pragma unroll
    for (int o = 16; o > 0; o >>= 1) v += __shfl_xor_sync(0xffffffffu, v, o);
    return v;
}
__device__ __forceinline__ void cp16(void* dst, const void* src) {
    uint32_t d = (uint32_t)__cvta_generic_to_shared(dst);
    asm volatile("cp.async.cg.shared.global [%0], [%1], 16;\n" :: "r"(d), "l"(src));
}
__device__ __forceinline__ uint2 f4_to_h4(float4 v) {
    __half2 lo = __floats2half2_rn(v.x, v.y);
    __half2 hi = __floats2half2_rn(v.z, v.w);
    uint2 r;
    r.x = *reinterpret_cast<uint32_t*>(&lo);
    r.y = *reinterpret_cast<uint32_t*>(&hi);
    return r;
}

// ---------------- 1) fused prep: LN, weight conversion, teacher norms -------
#define WN4 ((size_t)7 * DIM * CTD / 4)
#define WI4 ((size_t)DIM * CTD / 4)
#define WO4 ((size_t)CTD * CTD / 4)
#define LN_BLOCKS (MTOT * 8)
#define CW_TOTAL  (WN4 + WI4 + WO4)
#define CW_BLOCKS ((unsigned)((CW_TOTAL + 255) / 256))
#define PREP_BLOCKS (LN_BLOCKS + CW_BLOCKS + MTOT)

__global__ void __launch_bounds__(256) prep_kernel(
    const float* __restrict__ features,
    const float* __restrict__ ln_scale,
    const float* __restrict__ ln_bias,
    const float* __restrict__ wn,
    const float* __restrict__ wi,
    const float* __restrict__ wo,
    const float* __restrict__ teacher)
{
    if (blockIdx.x >= LN_BLOCKS + CW_BLOCKS) {
        // teacher norm^2 for one row
        int m = blockIdx.x - (LN_BLOCKS + CW_BLOCKS);
        int t = threadIdx.x;
        float4 y = reinterpret_cast<const float4*>(teacher + (size_t)m * CTD)[t];
        float n2 = y.x*y.x + y.y*y.y + y.z*y.z + y.w*y.w;
        __shared__ float s2[8];
        float w2 = warp_sum(n2);
        int w = t >> 5, lane = t & 31;
        if (lane == 0) s2[w] = w2;
        __syncthreads();
        if (t == 0) {
            float tot = 0.f;
#pragma unroll
            for (int i = 0; i < 8; i++) tot += s2[i];
            g_n2[m] = tot;
        }
        return;
    }
    if (blockIdx.x >= LN_BLOCKS) {
        size_t i = (size_t)(blockIdx.x - LN_BLOCKS) * 256 + threadIdx.x;
        if (i < WN4) {
            reinterpret_cast<uint2*>(g_wh)[i] =
                f4_to_h4(reinterpret_cast<const float4*>(wn)[i]);
        } else if (i < WN4 + WI4) {
            size_t j = i - WN4;
            reinterpret_cast<uint2*>(g_wh + (size_t)7 * DIM * CTD)[j] =
                f4_to_h4(reinterpret_cast<const float4*>(wi)[j]);
        } else if (i < WN4 + WI4 + WO4) {
            size_t j = i - WN4 - WI4;
            reinterpret_cast<uint2*>(g_woh)[j] =
                f4_to_h4(reinterpret_cast<const float4*>(wo)[j]);
        }
        return;
    }

    int l = blockIdx.x & 7;
    int m = blockIdx.x >> 3;
    int layer = (l < 7) ? (24 - 4 * l) : 24;
    const float4* x = reinterpret_cast<const float4*>(
        features + ((size_t)m * NLF + layer) * DIM);
    int t = threadIdx.x;

    float4 a = x[t];
    float4 b = x[t + 256];
    uint2* o = reinterpret_cast<uint2*>(g_xn + ((size_t)l * MTOT + m) * DIM);

    if (l == 7) {
        o[t] = f4_to_h4(a);
        o[t + 256] = f4_to_h4(b);
        return;
    }

    float s  = a.x + a.y + a.z + a.w + b.x + b.y + b.z + b.w;
    float ss = a.x*a.x + a.y*a.y + a.z*a.z + a.w*a.w
             + b.x*b.x + b.y*b.y + b.z*b.z + b.w*b.w;

    __shared__ float shs[8], shss[8];
    float ws  = warp_sum(s);
    float wss = warp_sum(ss);
    int w = t >> 5, lane = t & 31;
    if (lane == 0) { shs[w] = ws; shss[w] = wss; }
    __syncthreads();
    float tot = 0.f, tot2 = 0.f;
#pragma unroll
    for (int i = 0; i < 8; i++) { tot += shs[i]; tot2 += shss[i]; }

    float mu  = tot * (1.0f / DIM);
    float var = tot2 * (1.0f / DIM) - mu * mu;
    float rs  = rsqrtf(var + LN_EPSF);

    const float4* sc = reinterpret_cast<const float4*>(ln_scale + (size_t)l * DIM);
    const float4* bi = reinterpret_cast<const float4*>(ln_bias  + (size_t)l * DIM);
    float4 s0 = sc[t],       b0 = bi[t];
    float4 s1 = sc[t + 256], b1 = bi[t + 256];
    float4 o0, o1;
    o0.x = (a.x - mu) * rs * s0.x + b0.x;
    o0.y = (a.y - mu) * rs * s0.y + b0.y;
    o0.z = (a.z - mu) * rs * s0.z + b0.z;
    o0.w = (a.w - mu) * rs * s0.w + b0.w;
    o1.x = (b.x - mu) * rs * s1.x + b1.x;
    o1.y = (b.y - mu) * rs * s1.y + b1.y;
    o1.z = (b.z - mu) * rs * s1.z + b1.z;
    o1.w = (b.w - mu) * rs * s1.w + b1.w;
    o[t] = f4_to_h4(o0);
    o[t + 256] = f4_to_h4(o1);
}

// ---------------- 2) HFMA2 GEMM: 128x128x32 tile, 256 thr, 8Mx8N/thread -----
// 2 CTAs/SM. A dup (v,v) half2 pairs in smem; B fp16 [K,N] natural via cp.async.
// half2 accumulators flushed to fp32 regs every 8 K-tiles (K=256 window).
// MODE 0: g_xn[z] @ g_wh[z] -> z<7: g_vh slot z (fp16); z==7: g_vin + b_in
// MODE 1: g_fuse @ g_woh + vin + b_out; fused cosine partials -> g_part
#define KT 32
template<int NKT, int MODE>
__global__ void __launch_bounds__(256, 2) gemm_h5(
    const float* __restrict__ bias,
    const float* __restrict__ teacher)
{
    __shared__ __align__(16) uint32_t As2[2][KT][128];  // dup half2 pairs, 32 KB
    __shared__ __align__(16) __half   Bs[2][KT][128];   // 16 KB

    int tid = threadIdx.x;
    int m0 = blockIdx.y * 128, n0 = blockIdx.x * 128;
    int z = (MODE == 0) ? blockIdx.z : 0;

    const __half* A;
    const __half* B;
    if (MODE == 0) {
        A = g_xn + (size_t)z * MTOT * DIM;
        B = g_wh + (size_t)z * DIM * CTD;
    } else {
        A = g_fuse;
        B = g_woh;
    }
    const int lda = (MODE == 0) ? DIM : CTD;

    // A loader: thread t -> row t>>1, k-cols (t&1)*16 .. +15 (two uint4)
    int arow = tid >> 1, acol = (tid & 1) * 16;
    const __half* ag = A + (size_t)(m0 + arow) * lda + acol;
    // B loader: thread t -> krow t>>3, cols (t&7)*16 .. +15 (two cp16)
    int brow = tid >> 3, bcol = (tid & 7) * 16;
    const __half* bg = B + (size_t)brow * CTD + n0 + bcol;

    // compute mapping: ty 0..15 (8 m-rows), tx 0..15 (8 n-cols)
    int ty = tid >> 4, tx = tid & 15;

    float2  accf[8][4];
    __half2 acch[8][4];
#pragma unroll
    for (int i = 0; i < 8; i++)
#pragma unroll
        for (int j = 0; j < 4; j++) {
            accf[i][j] = make_float2(0.f, 0.f);
            acch[i][j] = __half2half2(__ushort_as_half(0));
        }

    uint4 pa0, pa1;

    auto store_a = [&](int buf) {
        const __half2* h0 = reinterpret_cast<const __half2*>(&pa0);
        const __half2* h1 = reinterpret_cast<const __half2*>(&pa1);
#pragma unroll
        for (int jj = 0; jj < 4; jj++) {
            __half2 dlo = __half2half2(__low2half(h0[jj]));
            __half2 dhi = __half2half2(__high2half(h0[jj]));
            As2[buf][acol + 2 * jj][arow]     = *reinterpret_cast<uint32_t*>(&dlo);
            As2[buf][acol + 2 * jj + 1][arow] = *reinterpret_cast<uint32_t*>(&dhi);
        }
#pragma unroll
        for (int jj = 0; jj < 4; jj++) {
            __half2 dlo = __half2half2(__low2half(h1[jj]));
            __half2 dhi = __half2half2(__high2half(h1[jj]));
            As2[buf][acol + 8 + 2 * jj][arow]     = *reinterpret_cast<uint32_t*>(&dlo);
            As2[buf][acol + 8 + 2 * jj + 1][arow] = *reinterpret_cast<uint32_t*>(&dhi);
        }
    };

    // ---- prologue: tile 0 into buf 0 ----
    pa0 = *reinterpret_cast<const uint4*>(ag);
    pa1 = *reinterpret_cast<const uint4*>(ag + 8);
    cp16(&Bs[0][brow][bcol], bg);
    cp16(&Bs[0][brow][bcol + 8], bg + 8);
    asm volatile("cp.async.commit_group;\n" ::: "memory");
    store_a(0);

    for (int kt = 0; kt < NKT; kt++) {
        int buf = kt & 1;
        asm volatile("cp.async.wait_group 0;\n" ::: "memory");
        __syncthreads();

        if (kt + 1 < NKT) {
            pa0 = *reinterpret_cast<const uint4*>(ag + (kt + 1) * KT);
            pa1 = *reinterpret_cast<const uint4*>(ag + (kt + 1) * KT + 8);
            const __half* bn = bg + (size_t)(kt + 1) * KT * CTD;
            cp16(&Bs[buf ^ 1][brow][bcol], bn);
            cp16(&Bs[buf ^ 1][brow][bcol + 8], bn + 8);
            asm volatile("cp.async.commit_group;\n" ::: "memory");
        }

#pragma unroll
        for (int k = 0; k < KT; k++) {
            __half2 a2[8], b2[4];
            *reinterpret_cast<uint4*>(&a2[0]) =
                *reinterpret_cast<const uint4*>(&As2[buf][k][ty * 8]);
            *reinterpret_cast<uint4*>(&a2[4]) =
                *reinterpret_cast<const uint4*>(&As2[buf][k][ty * 8 + 4]);
            *reinterpret_cast<uint4*>(&b2[0]) =
                *reinterpret_cast<const uint4*>(&Bs[buf][k][tx * 8]);
#pragma unroll
            for (int i = 0; i < 8; i++)
#pragma unroll
                for (int j = 0; j < 4; j++)
                    acch[i][j] = __hfma2(a2[i], b2[j], acch[i][j]);
        }

        if (kt + 1 < NKT) store_a(buf ^ 1);

        if ((kt & 7) == 7 || kt == NKT - 1) {
#pragma unroll
            for (int i = 0; i < 8; i++)
#pragma unroll
                for (int j = 0; j < 4; j++) {
                    float2 t = __half22float2(acch[i][j]);
                    accf[i][j].x += t.x;
                    accf[i][j].y += t.y;
                    acch[i][j] = __half2half2(__ushort_as_half(0));
                }
        }
    }

    // ---- epilogue: 8 rows x 8 cols per thread ----
#pragma unroll
    for (int i = 0; i < 8; i++) {
        int m = m0 + ty * 8 + i;
        int n = n0 + tx * 8;
        float4 v0, v1;
        v0.x = accf[i][0].x; v0.y = accf[i][0].y;
        v0.z = accf[i][1].x; v0.w = accf[i][1].y;
        v1.x = accf[i][2].x; v1.y = accf[i][2].y;
        v1.z = accf[i][3].x; v1.w = accf[i][3].y;
        if (MODE == 0) {
            if (z < 7) {
                uint2 h0 = f4_to_h4(v0);
                uint2 h1 = f4_to_h4(v1);
                uint4 hv = make_uint4(h0.x, h0.y, h1.x, h1.y);
                *reinterpret_cast<uint4*>(
                    g_vh + (size_t)m * (7 * CTD) + (size_t)z * CTD + n) = hv;
            } else {
                float4 b0 = *reinterpret_cast<const float4*>(bias + n);
                float4 b1 = *reinterpret_cast<const float4*>(bias + n + 4);
                v0.x += b0.x; v0.y += b0.y; v0.z += b0.z; v0.w += b0.w;
                v1.x += b1.x; v1.y += b1.y; v1.z += b1.z; v1.w += b1.w;
                float* dst = g_vin + (size_t)m * CTD + n;
                *reinterpret_cast<float4*>(dst)     = v0;
                *reinterpret_cast<float4*>(dst + 4) = v1;
            }
        } else {
            float4 b0 = *reinterpret_cast<const float4*>(bias + n);
            float4 b1 = *reinterpret_cast<const float4*>(bias + n + 4);
            const float* vin = g_vin + (size_t)m * CTD + n;
            float4 i0 = *reinterpret_cast<const float4*>(vin);
            float4 i1 = *reinterpret_cast<const float4*>(vin + 4);
            v0.x += b0.x + i0.x; v0.y += b0.y + i0.y;
            v0.z += b0.z + i0.z; v0.w += b0.w + i0.w;
            v1.x += b1.x + i1.x; v1.y += b1.y + i1.y;
            v1.z += b1.z + i1.z; v1.w += b1.w + i1.w;
            // fused cosine partials for this 8-col strip of row m
            const float* tr = teacher + (size_t)m * CTD + n;
            float4 t0 = *reinterpret_cast<const float4*>(tr);
            float4 t1 = *reinterpret_cast<const float4*>(tr + 4);
            float pd = v0.x*t0.x + v0.y*t0.y + v0.z*t0.z + v0.w*t0.w
                     + v1.x*t1.x + v1.y*t1.y + v1.z*t1.z + v1.w*t1.w;
            float pn = v0.x*v0.x + v0.y*v0.y + v0.z*v0.z + v0.w*v0.w
                     + v1.x*v1.x + v1.y*v1.y + v1.z*v1.z + v1.w*v1.w;
            // reduce across the 16 lanes sharing this row (tx = lane & 15)
#pragma unroll
            for (int o = 8; o > 0; o >>= 1) {
                pd += __shfl_xor_sync(0xffffffffu, pd, o);
                pn += __shfl_xor_sync(0xffffffffu, pn, o);
            }
            if (tx == 0) {
                float* dst = g_part + ((size_t)blockIdx.x * MTOT + m) * 2;
                dst[0] = pd;
                dst[1] = pn;
            }
        }
    }
}

// ---------------- 3) attention fuse: one warp per (m, head) ----------------
__global__ void __launch_bounds__(256) attn_kernel()
{
    int m = blockIdx.x;
    int h = threadIdx.x >> 5;
    int lane = threadIdx.x & 31;
    const __half* vrow = g_vh + (size_t)m * 7 * CTD + h * HDIM + lane * 4;

    float q[4], kv[6][4];
    {
        uint2 r = *reinterpret_cast<const uint2*>(vrow);
        float2 a = __half22float2(*reinterpret_cast<__half2*>(&r.x));
        float2 b = __half22float2(*reinterpret_cast<__half2*>(&r.y));
        q[0] = a.x * ATT_SCALE; q[1] = a.y * ATT_SCALE;
        q[2] = b.x * ATT_SCALE; q[3] = b.y * ATT_SCALE;
    }
#pragma unroll
    for (int l = 0; l < 6; l++) {
        uint2 r = *reinterpret_cast<const uint2*>(vrow + (size_t)(l + 1) * CTD);
        float2 a = __half22float2(*reinterpret_cast<__half2*>(&r.x));
        float2 b = __half22float2(*reinterpret_cast<__half2*>(&r.y));
        kv[l][0] = a.x; kv[l][1] = a.y; kv[l][2] = b.x; kv[l][3] = b.y;
    }

    float logit[6];
#pragma unroll
    for (int l = 0; l < 6; l++) {
        float p = q[0] * kv[l][0] + q[1] * kv[l][1]
                + q[2] * kv[l][2] + q[3] * kv[l][3];
        logit[l] = warp_sum(p);
    }

    float mx = -1e30f;
#pragma unroll
    for (int l = 0; l < 6; l++) mx = fmaxf(mx, logit[l]);
    float e[6], sum = 0.f;
#pragma unroll
    for (int l = 0; l < 6; l++) { e[l] = expf(logit[l] - mx); sum += e[l]; }
    float inv = 1.0f / sum;

    float f[4] = {0.f, 0.f, 0.f, 0.f};
#pragma unroll
    for (int l = 0; l < 6; l++) {
        float w = e[l] * inv;
#pragma unroll
        for (int d = 0; d < 4; d++) f[d] += w * kv[l][d];
    }

    __half2 lo = __floats2half2_rn(f[0], f[1]);
    __half2 hi = __floats2half2_rn(f[2], f[3]);
    uint2 outv;
    outv.x = *reinterpret_cast<uint32_t*>(&lo);
    outv.y = *reinterpret_cast<uint32_t*>(&hi);
    *reinterpret_cast<uint2*>(
        g_fuse + (size_t)m * CTD + h * HDIM + lane * 4) = outv;
}

// ---------------- 4) final: combine strips, cosine, deterministic mean ------
__global__ void __launch_bounds__(512) final_kernel(float* __restrict__ out)
{
    __shared__ float sh[512];
    int t = threadIdx.x;
    float s = 0.f;
    for (int m = t; m < MTOT; m += 512) {
        float dot = 0.f, n1 = 0.f;
#pragma unroll
        for (int st = 0; st < 8; st++) {
            const float* p = g_part + ((size_t)st * MTOT + m) * 2;
            dot += p[0];
            n1  += p[1];
        }
        float na = fmaxf(sqrtf(n1), COS_EPSF);
        float nb = fmaxf(sqrtf(g_n2[m]), COS_EPSF);
        s += dot / (na * nb);
    }
    sh[t] = s;
    __syncthreads();
    for (int o = 256; o > 0; o >>= 1) {
        if (t < o) sh[t] += sh[t + o];
        __syncthreads();
    }
    if (t == 0) out[0] = 1.0f - sh[0] / (float)MTOT;
}

// ---------------- launch ----------------
extern "C" void kernel_launch(void* const* d_in, const int* in_sizes, int n_in,
                              void* d_out, int out_size)
{
    const float* features = (const float*)d_in[0];
    const float* teacher  = (const float*)d_in[1];
    const float* ln_scale = (const float*)d_in[2];
    const float* ln_bias  = (const float*)d_in[3];
    const float* w_norm   = (const float*)d_in[4];
    const float* w_in     = (const float*)d_in[5];
    const float* b_in     = (const float*)d_in[6];
    const float* w_out    = (const float*)d_in[7];
    const float* b_out    = (const float*)d_in[8];
    float* out = (float*)d_out;

    prep_kernel<<<PREP_BLOCKS, 256>>>(
        features, ln_scale, ln_bias, w_norm, w_in, w_out, teacher);
    gemm_h5<DIM / KT, 0><<<dim3(CTD / 128, MTOT / 128, 8), 256>>>(b_in, nullptr);
    attn_kernel<<<MTOT, 256>>>();
    gemm_h5<CTD / KT, 1><<<dim3(CTD / 128, MTOT / 128, 1), 256>>>(b_out, teacher);
    final_kernel<<<1, 512>>>(out);
}